// round 14
// baseline (speedup 1.0000x reference)
#include <cuda_runtime.h>
#include <math.h>

#define B_   16
#define N_   2048
#define K_   16
#define EPS_ 1e-8f

// Output layout (tuple flattened in order):
//   psi_prime : B*N*2  floats  @ 0
//   features  : B*N*5  floats  @ 65536
//   knn_idx   : B*N*16 floats  @ 229376
#define PSI_OFF  0
#define FEAT_OFF (B_ * N_ * 2)
#define KNN_OFF  (B_ * N_ * 2 + B_ * N_ * 5)

typedef unsigned long long u64;
typedef unsigned int u32;

#define SUB_ (N_ / 2)          // candidates per thread (2 threads/query)
#define NWIN (SUB_ / 8)        // 8-candidate windows per thread (128)

// SOA candidate data for the KNN kernel.
__device__ float g_x [B_ * N_];
__device__ float g_y [B_ * N_];
__device__ float g_sq[B_ * N_];

// ---------------------------------------------------------------------------
// Kernel 1: features + encoder (tiny MLP) + SOA coord scratch.
// ---------------------------------------------------------------------------
__global__ void encode_kernel(const float* __restrict__ coords,
                              const float* __restrict__ demands,
                              const float* __restrict__ capacity,
                              const float* __restrict__ Wa,
                              const float* __restrict__ ba,
                              const float* __restrict__ W1,
                              const float* __restrict__ b1,
                              const float* __restrict__ W2,
                              const float* __restrict__ b2,
                              float* __restrict__ out)
{
    int b = blockIdx.y;
    int n = blockIdx.x * blockDim.x + threadIdx.x;
    if (n >= N_) return;

    __shared__ float sWa[10], sba[2], sW1[80], sb1[16], sW2[16], sb2_s;
    int t = threadIdx.x;
    if (t < 10) sWa[t] = Wa[t];
    if (t < 2)  sba[t] = ba[t];
    if (t < 80) sW1[t] = W1[t];
    if (t < 16) { sb1[t] = b1[t]; sW2[t] = W2[t]; }
    if (t == 0) sb2_s = b2[0];
    __syncthreads();

    const float* cp = coords + ((long long)b * N_ + n) * 2;
    float x = cp[0], y = cp[1];

    // SOA scratch for knn; sq = rn(rn(x*x) + rn(y*y)) (reference rounding)
    float sq = __fadd_rn(__fmul_rn(x, x), __fmul_rn(y, y));
    g_x [b * N_ + n] = x;
    g_y [b * N_ + n] = y;
    g_sq[b * N_ + n] = sq;

    float dx0 = coords[(long long)b * N_ * 2 + 0];
    float dy0 = coords[(long long)b * N_ * 2 + 1];
    float rx = x - dx0, ry = y - dy0;
    float dist = sqrtf(rx * rx + ry * ry + EPS_);
    float ang  = atan2f(ry, rx);
    float dem  = demands[(long long)b * N_ + n] / capacity[b];

    float f0 = x, f1 = y, f2 = dem, f3 = dist, f4 = ang;

    float* fo = out + FEAT_OFF + ((long long)b * N_ + n) * 5;
    fo[0] = f0; fo[1] = f1; fo[2] = f2; fo[3] = f3; fo[4] = f4;

    float p0 = sba[0] + f0*sWa[0] + f1*sWa[1] + f2*sWa[2] + f3*sWa[3] + f4*sWa[4];
    float p1 = sba[1] + f0*sWa[5] + f1*sWa[6] + f2*sWa[7] + f3*sWa[8] + f4*sWa[9];
    float nrm = sqrtf(p0 * p0 + p1 * p1);
    float inv = 1.0f / (nrm + EPS_);
    p0 *= inv; p1 *= inv;

    float theta = sb2_s;
    #pragma unroll
    for (int h = 0; h < 16; ++h) {
        const float* w = sW1 + h * 5;
        float a = sb1[h] + f0*w[0] + f1*w[1] + f2*w[2] + f3*w[3] + f4*w[4];
        theta += tanhf(a) * sW2[h];
    }
    float c = cosf(theta), s = sinf(theta);

    float* po = out + PSI_OFF + ((long long)b * N_ + n) * 2;
    po[0] = c * p0 - s * p1;
    po[1] = s * p0 + c * p1;
}

// ---------------------------------------------------------------------------
// KNN helpers
// ---------------------------------------------------------------------------

// Monotone map: float bits -> u32 whose unsigned order == float order.
__device__ __forceinline__ u32 fmap(u32 b) {
    return b ^ ((u32)((int)b >> 31) | 0x80000000u);
}

// d2 bit-exact with the reference:
//   t = rn(xq*xj); dot = fma(yq,yj,t); s = rn(sqq+sqj)
//   ref rn(s - rn(2*dot)) == rn(s - 2*dot) == fma(-2, dot, s)   [2*dot exact]
#define D2_OF(xv, yv, sv) \
    __fmaf_rn(-2.0f, __fmaf_rn(yq, (yv), __fmul_rn(xq, (xv))), \
              __fadd_rn(sqq, (sv)))

// R2/R4-proven STABLE shift-insert into ascending (bd, bi). Strict '<'
// everywhere: with scan-monotonic j, an incoming equal-d2 candidate has
// larger j than every list entry, ranks below them (top_k stable order),
// and is correctly rejected; the suffix shifts together so equal-valued
// entries never leapfrog.
#define INSERT(dv, jv)                                       \
    do {                                                     \
        float d2v = (dv); int jj = (jv);                     \
        _Pragma("unroll")                                    \
        for (int k = K_ - 1; k > 0; --k) {                   \
            bool shift = d2v < bd[k - 1];                    \
            float sd = shift ? bd[k - 1] : d2v;              \
            int   si = shift ? bi[k - 1] : jj;               \
            bool place = d2v < bd[k];                        \
            bd[k] = place ? sd : bd[k];                      \
            bi[k] = place ? si : bi[k];                      \
        }                                                    \
        if (d2v < bd[0]) { bd[0] = d2v; bi[0] = jj; }        \
    } while (0)

// ---------------------------------------------------------------------------
// Kernel 2: KNN top-16, direct tau-gated insertion, 2 threads per query.
// Thread p scans half [p*1024, (p+1)*1024) in 8-candidate windows (6
// coalesced LDG.128 each). tau = min(own 16th, partner 16th), refreshed
// every window by one shfl (convergent at window top). Gate 'min8 <= tau'
// (then 'e <= tau' per candidate) admits every final-top-16 element:
// tau >= running global 16th and the gate is '<='. Admitted candidates go
// through the stable shift-insert (registers only - no buffer, no ballot,
// no flush networks). Cross-half ties resolved at the final partner merge
// on u64 (fmap(d2), j) keys (R7/R10-proven network).
// ---------------------------------------------------------------------------
__global__ void __launch_bounds__(128)
knn_kernel(float* __restrict__ out_knn)
{
    int qid = blockIdx.x * 64 + (threadIdx.x >> 1);  // global query id
    int p   = threadIdx.x & 1;                       // candidate-half
    int b   = qid >> 11;
    int q   = qid & (N_ - 1);

    const float* bx = g_x  + b * N_;
    const float* by = g_y  + b * N_;
    const float* bs = g_sq + b * N_;

    float xq  = __ldg(&bx[q]);
    float yq  = __ldg(&by[q]);
    float sqq = __ldg(&bs[q]);

    const float4* x4 = (const float4*)(bx + p * SUB_);
    const float4* y4 = (const float4*)(by + p * SUB_);
    const float4* s4 = (const float4*)(bs + p * SUB_);
    int jbase = p * SUB_;

    float bd[K_];
    int   bi[K_];
    #pragma unroll
    for (int k = 0; k < K_; ++k) { bd[k] = 3.0e30f; bi[k] = 0; }

    for (int i = 0; i < NWIN; ++i) {
        float4 xa = __ldg(&x4[2 * i]);
        float4 xb = __ldg(&x4[2 * i + 1]);
        float4 ya = __ldg(&y4[2 * i]);
        float4 yb = __ldg(&y4[2 * i + 1]);
        float4 sa = __ldg(&s4[2 * i]);
        float4 sb = __ldg(&s4[2 * i + 1]);

        // shared tau: min of own and partner 16th (convergent at window top)
        float own15 = bd[K_ - 1];
        float tau = fminf(own15, __shfl_xor_sync(0xffffffffu, own15, 1));

        float e0 = D2_OF(xa.x, ya.x, sa.x);
        float e1 = D2_OF(xa.y, ya.y, sa.y);
        float e2 = D2_OF(xa.z, ya.z, sa.z);
        float e3 = D2_OF(xa.w, ya.w, sa.w);
        float e4 = D2_OF(xb.x, yb.x, sb.x);
        float e5 = D2_OF(xb.y, yb.y, sb.y);
        float e6 = D2_OF(xb.z, yb.z, sb.z);
        float e7 = D2_OF(xb.w, yb.w, sb.w);

        int j0 = jbase + 8 * i;
        // self-exclusion, one rare branch per 8-window
        if ((unsigned)(q - j0) < 8u) {
            int r = q - j0;
            if (r == 0) e0 = 2.0e30f;  if (r == 1) e1 = 2.0e30f;
            if (r == 2) e2 = 2.0e30f;  if (r == 3) e3 = 2.0e30f;
            if (r == 4) e4 = 2.0e30f;  if (r == 5) e5 = 2.0e30f;
            if (r == 6) e6 = 2.0e30f;  if (r == 7) e7 = 2.0e30f;
        }

        float m8 = fminf(fminf(fminf(e0, e1), fminf(e2, e3)),
                         fminf(fminf(e4, e5), fminf(e6, e7)));
        // '<=' so equal-d2 candidates (which may outrank the partner's
        // equal 16th by smaller j) are never gated out; INSERT internally
        // rejects anything not strictly better than own 16th.
        if (m8 <= tau) {
            if (e0 <= tau) INSERT(e0, j0);
            if (e1 <= tau) INSERT(e1, j0 + 1);
            if (e2 <= tau) INSERT(e2, j0 + 2);
            if (e3 <= tau) INSERT(e3, j0 + 3);
            if (e4 <= tau) INSERT(e4, j0 + 4);
            if (e5 <= tau) INSERT(e5, j0 + 5);
            if (e6 <= tau) INSERT(e6, j0 + 6);
            if (e7 <= tau) INSERT(e7, j0 + 7);
        }
    }

    // Pack to total-order u64 keys: (fmap(d2) << 32) | j. bd ascending and
    // stable-insert order => L ascending (ties: smaller j first).
    u64 L[16];
    #pragma unroll
    for (int k = 0; k < K_; ++k)
        L[k] = ((u64)fmap(__float_as_uint(bd[k])) << 32) | (u32)bi[k];

    // Merge partner halves (lane^1): min-pair vs partner's reversed sorted
    // list -> bitonic -> clean. Both lanes end with the identical top-16.
    #pragma unroll
    for (int i = 0; i < 16; ++i) {
        u64 other = __shfl_xor_sync(0xffffffffu, L[15 - i], 1);
        u64 a = L[i];
        L[i] = (a < other) ? a : other;
    }
    #pragma unroll
    for (int j = 8; j > 0; j >>= 1) {
        #pragma unroll
        for (int i = 0; i < 16; ++i) {
            int l = i ^ j;
            if (l > i) {
                u64 a = L[i], b2 = L[l];
                bool sw = a > b2;
                L[i] = sw ? b2 : a;
                L[l] = sw ? a : b2;
            }
        }
    }

    // Each partner lane writes half the 16 outputs.
    float* o = out_knn + ((long long)b * N_ + q) * K_;
    #pragma unroll
    for (int k = 0; k < 8; ++k) {
        int kk = p * 8 + k;
        o[kk] = (float)(u32)(L[kk] & 0xFFFFFFFFu);
    }
}

// ---------------------------------------------------------------------------
extern "C" void kernel_launch(void* const* d_in, const int* in_sizes, int n_in,
                              void* d_out, int out_size)
{
    const float* coords   = (const float*)d_in[0];
    const float* demands  = (const float*)d_in[1];
    const float* capacity = (const float*)d_in[2];
    const float* Wa       = (const float*)d_in[3];
    const float* ba       = (const float*)d_in[4];
    const float* W1       = (const float*)d_in[5];
    const float* b1       = (const float*)d_in[6];
    const float* W2       = (const float*)d_in[7];
    const float* b2       = (const float*)d_in[8];
    float* out = (float*)d_out;

    encode_kernel<<<dim3(N_ / 256, B_), 256>>>(coords, demands, capacity,
                                               Wa, ba, W1, b1, W2, b2, out);
    // B*N queries x 2 threads each; 128-thread blocks (64 queries/block)
    knn_kernel<<<dim3(B_ * N_ * 2 / 128), 128>>>(out + KNN_OFF);
}